// round 1
// baseline (speedup 1.0000x reference)
#include <cuda_runtime.h>

// Problem constants
#define T_   24      // HIST
#define D_   256     // SKIP
#define E_   128     // END
#define O_   2       // OUT_DIM
#define KK   13      // KERNEL
#define F_   12      // future steps
#define NB   4096    // B*N nodes

#define THREADS 256
#define DC      32   // d-chunk size for W1 staging
#define WROW    132  // padded row stride (floats) for ws tile: 16B-aligned, 4-way-max STS conflict

typedef unsigned long long u64;

__device__ __forceinline__ void fma2(u64 &d, u64 a, u64 b) {
    // packed f32x2 fma (Blackwell): 2 fp32 FMAs per instruction
    asm("fma.rn.f32x2 %0, %1, %2, %0;" : "+l"(d) : "l"(a), "l"(b));
}
__device__ __forceinline__ u64 pack2(float v) {
    u64 r; asm("mov.b64 %0, {%1, %1};" : "=l"(r) : "f"(v)); return r;
}
__device__ __forceinline__ void unpack2(u64 v, float &lo, float &hi) {
    asm("mov.b64 {%0, %1}, %2;" : "=f"(lo), "=f"(hi) : "l"(v));
}

__global__ __launch_bounds__(THREADS)
void tcnn_moe_kernel(const float* __restrict__ x,
                     const int*   __restrict__ labels,
                     const float* __restrict__ W1,
                     const float* __restrict__ b1,
                     const float* __restrict__ W2,
                     const float* __restrict__ b2,
                     float*       __restrict__ out)
{
    __shared__ float xs[T_ * D_];     // 24 KB: relu(x); later aliased as h (24x128)
    __shared__ float ws[DC * WROW];   // 16.5 KB: W1 chunk, j-major [j][e]
    __shared__ float red[4 * 24];     // cross-warp reduction for layer 2

    const int node = blockIdx.x;          // 0..4095
    const int tid  = threadIdx.x;
    const int lane = tid & 31;
    const int warp = tid >> 5;            // 0..7
    const int lbl  = labels[node];        // expert id 0..7

    // ---------------- stage relu(x) into smem (coalesced float4) ----------------
    {
        const float4* xg  = reinterpret_cast<const float4*>(x + (size_t)node * (T_ * D_));
        float4*       xs4 = reinterpret_cast<float4*>(xs);
        #pragma unroll
        for (int i = 0; i < (T_ * D_ / 4) / THREADS; i++) {   // 6 iters
            int idx = tid + i * THREADS;
            float4 v = xg[idx];
            v.x = fmaxf(v.x, 0.f); v.y = fmaxf(v.y, 0.f);
            v.z = fmaxf(v.z, 0.f); v.w = fmaxf(v.w, 0.f);
            xs4[idx] = v;
        }
    }

    // ---------------- layer 1: h[t][e] = relu(b1[e] + sum_d xr[t][d]*W1[e][d]) ----
    // warp w owns t in {3w, 3w+1, 3w+2}; lane owns e in [4*lane, 4*lane+4) as 2 f32x2 pairs
    u64 acc[3][2] = {{0ull,0ull},{0ull,0ull},{0ull,0ull}};   // packed zeros == {0.f,0.f}

    const float* W1g = W1 + (size_t)lbl * (E_ * D_);
    const int t0 = warp * 3;
    const int e0 = lane * 4;

    for (int d0 = 0; d0 < D_; d0 += DC) {
        __syncthreads();
        // fill ws[j][e] = W1[e][d0+j]; global reads coalesced (32-float runs per e)
        #pragma unroll
        for (int i = tid; i < DC * E_; i += THREADS) {   // 16 iters
            int e = i >> 5;         // i / DC (DC==32)
            int j = i & (DC - 1);
            ws[j * WROW + e] = W1g[e * D_ + d0 + j];
        }
        __syncthreads();

        const float* xr = xs + t0 * D_ + d0;
        #pragma unroll
        for (int j = 0; j < DC; j++) {
            u64 xp0 = pack2(xr[j]);            // warp-uniform broadcast LDS
            u64 xp1 = pack2(xr[D_ + j]);
            u64 xp2 = pack2(xr[2 * D_ + j]);
            // one LDS.128 -> two packed f32x2 weight operands (conflict-free: 528B row stride)
            ulonglong2 wv = *reinterpret_cast<const ulonglong2*>(ws + j * WROW + e0);
            fma2(acc[0][0], xp0, wv.x);  fma2(acc[0][1], xp0, wv.y);
            fma2(acc[1][0], xp1, wv.x);  fma2(acc[1][1], xp1, wv.y);
            fma2(acc[2][0], xp2, wv.x);  fma2(acc[2][1], xp2, wv.y);
        }
    }

    __syncthreads();   // all warps done reading xs -> safe to alias as hs

    // bias + relu, store h into smem (alias of xs): hs[t*128 + e]
    float* hs = xs;
    {
        float4 bb = *reinterpret_cast<const float4*>(b1 + lbl * E_ + e0);
        #pragma unroll
        for (int i = 0; i < 3; i++) {
            float a0, a1, a2, a3;
            unpack2(acc[i][0], a0, a1);
            unpack2(acc[i][1], a2, a3);
            float4 h4;
            h4.x = fmaxf(a0 + bb.x, 0.f);
            h4.y = fmaxf(a1 + bb.y, 0.f);
            h4.z = fmaxf(a2 + bb.z, 0.f);
            h4.w = fmaxf(a3 + bb.w, 0.f);
            *reinterpret_cast<float4*>(hs + (t0 + i) * E_ + e0) = h4;
        }
    }
    __syncthreads();

    // ---------------- layer 2: out[f][o] = b2[o] + sum_{k,e} h[f+k][e]*W2[o][e][k] ----
    // e-parallel across 128 threads (warps 0-3); shuffle + smem reduce over e.
    if (warp < 4) {
        const int e = tid;   // 0..127
        float hreg[T_];
        #pragma unroll
        for (int t = 0; t < T_; t++) hreg[t] = hs[t * E_ + e];   // conflict-free

        const float* W2g = W2 + (size_t)lbl * (O_ * E_ * KK);
        #pragma unroll
        for (int o = 0; o < O_; o++) {
            float w2r[KK];
            #pragma unroll
            for (int k = 0; k < KK; k++) w2r[k] = W2g[(o * E_ + e) * KK + k];

            float accf[F_];
            #pragma unroll
            for (int f = 0; f < F_; f++) {
                float s = 0.f;
                #pragma unroll
                for (int k = 0; k < KK; k++) s = fmaf(hreg[f + k], w2r[k], s);
                accf[f] = s;
            }
            #pragma unroll
            for (int f = 0; f < F_; f++) {
                float s = accf[f];
                #pragma unroll
                for (int off = 16; off > 0; off >>= 1)
                    s += __shfl_xor_sync(0xffffffffu, s, off);
                if (lane == 0) red[warp * 24 + f * 2 + o] = s;
            }
        }
    }
    __syncthreads();

    if (tid < 24) {   // tid = f*2 + o
        int o = tid & 1;
        float s = red[tid] + red[24 + tid] + red[48 + tid] + red[72 + tid];
        s += b2[lbl * O_ + o];
        out[(size_t)node * (F_ * O_) + tid] = s;
    }
}

extern "C" void kernel_launch(void* const* d_in, const int* in_sizes, int n_in,
                              void* d_out, int out_size) {
    const float* x      = (const float*)d_in[0];   // (8,512,24,256) f32
    const int*   labels = (const int*)  d_in[1];   // (8,512) i32
    const float* W1     = (const float*)d_in[2];   // (8,128,256)
    const float* b1     = (const float*)d_in[3];   // (8,128)
    const float* W2     = (const float*)d_in[4];   // (8,2,128,13)
    const float* b2     = (const float*)d_in[5];   // (8,2)
    float* out = (float*)d_out;                    // (8,512,12,2) f32

    tcnn_moe_kernel<<<NB, THREADS>>>(x, labels, W1, b1, W2, b2, out);
}